// round 10
// baseline (speedup 1.0000x reference)
#include <cuda_runtime.h>
#include <stdint.h>

// Problem geometry (x: (32, 7, 512, 512) fp32; per-(B,C) slice quantile over H*W)
#define MAX_SLICES 224
#define N_PER      262144           // 512*512
#define M_SAMP     4096
#define NGROUP     512              // sample groups of 8 contiguous floats
#define CAND_MAX   32768

// Sample-rank brackets among 4096 sorted samples.
#define R_LO 100
#define R_HI 3995

#define NBIN 4096                   // top-12 bits of monotone key

// work partition: two-phase tickets, 64KB chunks
#define GBLK   16                   // gather chunks per slice
#define GCHUNK (N_PER / GBLK)       // 16384 elements
#define NBLKN  16                   // normalize chunks per slice
#define NCHUNK (N_PER / NBLKN)      // 16384 elements
#define TPS    (GBLK + NBLKN)       // 32
#define STASH  10                   // per-thread stash (mean ~1.6 of 64 elems)
#define SROW   (STASH + 1)          // padded row, conflict-free
#define OVF    512                  // per-block overflow fallback

// ---- static device scratch (no allocations allowed) ----
__device__ float    g_win[MAX_SLICES][2];              // w1 (lo tail), w2 (hi tail)
__device__ unsigned g_ncand[MAX_SLICES][2];
__device__ float    g_cand[MAX_SLICES][2][CAND_MAX];
__device__ float    g_q[MAX_SLICES][2];
__device__ unsigned g_ticket;
__device__ unsigned g_done[MAX_SLICES];
__device__ unsigned g_flag[MAX_SLICES];

// Monotone float <-> uint key
__device__ __forceinline__ unsigned fkey(float f) {
    unsigned u = __float_as_uint(f);
    return (u & 0x80000000u) ? ~u : (u | 0x80000000u);
}
__device__ __forceinline__ float funkey(unsigned k) {
    return (k & 0x80000000u) ? __uint_as_float(k & 0x7FFFFFFFu)
                             : __uint_as_float(~k);
}
__device__ __forceinline__ unsigned poll_u32(const unsigned* p) {
    unsigned v;
    asm volatile("ld.global.cg.u32 %0, [%1];" : "=r"(v) : "l"(p) : "memory");
    return v;
}

// ============================================================
// Kernel 1: per-slice sample histogram -> tail thresholds w1, w2
// ============================================================
__global__ void sample_kernel(const float* __restrict__ x) {
    __shared__ unsigned hist[NBIN];
    __shared__ unsigned toff[257];
    __shared__ unsigned sh_bin[2];
    __shared__ unsigned wsum[8];

    int slice = blockIdx.x;
    int tid = threadIdx.x;
    const float* xs = x + (size_t)slice * N_PER;

    if (slice == 0 && tid == 0) g_ticket = 0;

    for (int i = tid; i < NBIN; i += 256) hist[i] = 0;
    __syncthreads();

    #pragma unroll
    for (int g = tid; g < NGROUP; g += 256) {
        const float4* gp = (const float4*)(xs + (size_t)g * (N_PER / NGROUP));
        #pragma unroll
        for (int j = 0; j < 2; j++) {
            float4 v = gp[j];
            atomicAdd(&hist[fkey(v.x) >> 20], 1u);
            atomicAdd(&hist[fkey(v.y) >> 20], 1u);
            atomicAdd(&hist[fkey(v.z) >> 20], 1u);
            atomicAdd(&hist[fkey(v.w) >> 20], 1u);
        }
    }
    __syncthreads();

    unsigned s = 0;
    #pragma unroll
    for (int b = 0; b < 16; b++) s += hist[tid * 16 + b];

    int lane = tid & 31, wrp = tid >> 5;
    unsigned cum = s;
    #pragma unroll
    for (int o = 1; o < 32; o <<= 1) {
        unsigned t = __shfl_up_sync(0xffffffffu, cum, o);
        if (lane >= o) cum += t;
    }
    if (lane == 31) wsum[wrp] = cum;
    __syncthreads();
    if (tid == 0) {
        unsigned acc = 0;
        #pragma unroll
        for (int w = 0; w < 8; w++) { unsigned t = wsum[w]; wsum[w] = acc; acc += t; }
    }
    __syncthreads();
    toff[tid] = wsum[wrp] + cum - s;
    if (tid == 255) toff[256] = M_SAMP;
    __syncthreads();

    const int ranks[2] = {R_LO, R_HI};
    if (tid < 2) {
        unsigned R = (unsigned)ranks[tid];
        int lo = 0, hi = 256;
        while (hi - lo > 1) {
            int mid = (lo + hi) >> 1;
            if (toff[mid] <= R) lo = mid; else hi = mid;
        }
        unsigned acc = toff[lo];
        int bin = lo * 16;
        #pragma unroll
        for (int b = 0; b < 16; b++) {
            unsigned h = hist[lo * 16 + b];
            if (acc + h > R) { bin = lo * 16 + b; break; }
            acc += h;
        }
        sh_bin[tid] = (unsigned)bin;
    }
    __syncthreads();

    if (tid == 0) {
        g_win[slice][0] = funkey((sh_bin[0] + 1u) << 20);  // w1: upper edge
        g_win[slice][1] = funkey(sh_bin[1] << 20);         // w2: lower edge
        g_ncand[slice][0] = 0; g_ncand[slice][1] = 0;
        g_done[slice] = 0;
        g_flag[slice] = 0;
    }
}

// ============================================================
// Inline select: exact radix-select among candidates of (slice, w).
// w=0: candidates are ALL f < w1  -> base count 0.
// w=1: candidates are ALL f >= w2 -> base count N_PER - n.
// ============================================================
__device__ void do_select(int slice, int w, unsigned* hist, unsigned* tsum,
                          unsigned* red_u, volatile unsigned* sh2) {
    int tid = threadIdx.x;
    unsigned n_raw = g_ncand[slice][w];
    unsigned n = n_raw > CAND_MAX ? CAND_MAX : n_raw;
    unsigned cnt = (w == 0) ? 0u : (unsigned)N_PER - n_raw;

    double pos  = (w == 0) ? 0.01 * (double)(N_PER - 1) : 0.99 * (double)(N_PER - 1);
    long long K = (long long)pos;
    double frac = pos - (double)K;

    if (n < 2) {
        if (tid == 0) g_q[slice][w] = (n == 1) ? g_cand[slice][w][0] : 0.0f;
        return;
    }
    long long rl = K - (long long)cnt;
    if (rl < 0) rl = 0;
    if (rl > (long long)n - 2) rl = (long long)n - 2;
    int r = (int)rl;
    const float* cand = g_cand[slice][w];

    unsigned prefix = 0, pmask = 0;
    int rrem = r;
    const int shifts[3] = {21, 10, 0};
    const int bitsv[3]  = {11, 11, 10};
    #pragma unroll
    for (int p = 0; p < 3; p++) {
        int shift = shifts[p];
        unsigned nb = 1u << bitsv[p];
        unsigned dmask = nb - 1u;
        unsigned per = nb / 256;
        for (unsigned i = tid; i < 2048; i += 256) hist[i] = 0;
        __syncthreads();
        for (unsigned i = tid; i < n; i += 256) {
            unsigned u = fkey(cand[i]);
            if ((u & pmask) == prefix)
                atomicAdd(&hist[(u >> shift) & dmask], 1u);
        }
        __syncthreads();
        unsigned s = 0;
        for (unsigned q2 = 0; q2 < per; q2++) s += hist[tid * per + q2];
        tsum[tid] = s;
        __syncthreads();

        if (tid < 32) {
            unsigned part[8];
            unsigned ls = 0;
            #pragma unroll
            for (int j = 0; j < 8; j++) { part[j] = tsum[tid * 8 + j]; ls += part[j]; }
            unsigned cum = ls;
            #pragma unroll
            for (int o = 1; o < 32; o <<= 1) {
                unsigned t = __shfl_up_sync(0xffffffffu, cum, o);
                if (tid >= o) cum += t;
            }
            unsigned excl = cum - ls;
            unsigned ball = __ballot_sync(0xffffffffu, cum > (unsigned)rrem);
            int cross = __ffs(ball) - 1;
            if (tid == cross) {
                unsigned acc = excl;
                int tc = tid * 8;
                #pragma unroll
                for (int j = 0; j < 8; j++) {
                    if (acc + part[j] > (unsigned)rrem) { tc = tid * 8 + j; break; }
                    acc += part[j];
                }
                unsigned d = (unsigned)tc * per;
                for (unsigned b = 0; b < per; b++) {
                    unsigned h = hist[tc * per + b];
                    if (acc + h > (unsigned)rrem) { d = (unsigned)tc * per + b; break; }
                    acc += h;
                }
                sh2[0] = d;
                sh2[1] = (unsigned)rrem - acc;
            }
        }
        __syncthreads();
        prefix |= sh2[0] << shift;
        pmask  |= dmask << shift;
        rrem = (int)sh2[1];
        __syncthreads();
    }
    unsigned v0key = prefix;

    unsigned cle = 0, mgt = 0xFFFFFFFFu;
    for (unsigned i = tid; i < n; i += 256) {
        unsigned u = fkey(cand[i]);
        cle += (u <= v0key);
        if (u > v0key && u < mgt) mgt = u;
    }
    red_u[tid] = cle; __syncthreads();
    for (int o = 128; o; o >>= 1) {
        if (tid < o) red_u[tid] += red_u[tid + o];
        __syncthreads();
    }
    unsigned cle_tot = red_u[0]; __syncthreads();
    red_u[tid] = mgt; __syncthreads();
    for (int o = 128; o; o >>= 1) {
        if (tid < o) red_u[tid] = (red_u[tid + o] < red_u[tid]) ? red_u[tid + o] : red_u[tid];
        __syncthreads();
    }
    unsigned mgt_tot = red_u[0];
    __syncthreads();

    if (tid == 0) {
        unsigned v1key = (cle_tot >= (unsigned)(r + 2)) ? v0key
                       : ((mgt_tot != 0xFFFFFFFFu) ? mgt_tot : v0key);
        double v0 = (double)funkey(v0key);
        double v1 = (double)funkey(v1key);
        g_q[slice][w] = (float)(v0 + frac * (v1 - v0));
    }
}

// ============================================================
// Mega kernel: tickets [0, slices*GBLK) gather (slice-ascending);
// remaining tickets normalize in REVERSE slice order so the
// most-recently-gathered slices (L2-hot) are normalized first.
// ============================================================
__global__ void __launch_bounds__(256) mega_kernel(const float* __restrict__ x,
                                                   float* __restrict__ out) {
    __shared__ float stL[256 * SROW];        // 11.3 KB
    __shared__ float stH[256 * SROW];        // 11.3 KB (aliased in select)
    __shared__ float ovfL[OVF], ovfH[OVF];   // 4 KB
    __shared__ unsigned s_u[16];
    __shared__ unsigned wsumL[8], wsumH[8];
    __shared__ float s_q[2];

    int tid = threadIdx.x;
    int lane = tid & 31, wrp = tid >> 5;
    int slices = gridDim.x / TPS;
    unsigned gather_total = (unsigned)(GBLK * slices);

    if (tid == 0) {
        s_u[0] = atomicAdd(&g_ticket, 1u);
        s_u[1] = 0; s_u[2] = 0;
    }
    __syncthreads();
    unsigned ticket = s_u[0];

    if (ticket < gather_total) {
        // ---------------- gather role ----------------
        int slice = (int)(ticket / GBLK);
        int part  = (int)(ticket % GBLK);
        const float4* xs = (const float4*)(x + (size_t)slice * N_PER
                                             + (size_t)part * GCHUNK);
        float w1 = g_win[slice][0];
        float w2 = g_win[slice][1];

        float* pL = &stL[tid * SROW];
        float* pH = &stH[tid * SROW];
        unsigned nl = 0, nh = 0;
        // 16 float4 per thread; batch 4 loads for MLP
        #pragma unroll 4
        for (int k = 0; k < GCHUNK / 4 / 256; k++) {
            float4 v = xs[tid + k * 256];
            float vv[4] = {v.x, v.y, v.z, v.w};
            #pragma unroll
            for (int c = 0; c < 4; c++) {
                float f = vv[c];
                if (f < w1) {
                    if (nl < STASH) pL[nl++] = f;
                    else { unsigned o = atomicAdd(&s_u[1], 1u); if (o < OVF) ovfL[o] = f; }
                }
                if (f >= w2) {
                    if (nh < STASH) pH[nh++] = f;
                    else { unsigned o = atomicAdd(&s_u[2], 1u); if (o < OVF) ovfH[o] = f; }
                }
            }
        }

        // block exclusive scan of stash counts
        unsigned cumL = nl, cumH = nh;
        #pragma unroll
        for (int o = 1; o < 32; o <<= 1) {
            unsigned tL = __shfl_up_sync(0xffffffffu, cumL, o);
            unsigned tH = __shfl_up_sync(0xffffffffu, cumH, o);
            if (lane >= o) { cumL += tL; cumH += tH; }
        }
        if (lane == 31) { wsumL[wrp] = cumL; wsumH[wrp] = cumH; }
        __syncthreads();

        if (tid == 0) {
            unsigned aL = 0, aH = 0;
            #pragma unroll
            for (int w = 0; w < 8; w++) {
                unsigned tL = wsumL[w], tH = wsumH[w];
                wsumL[w] = aL; wsumH[w] = aH;
                aL += tL; aH += tH;
            }
            unsigned ovl = s_u[1] < OVF ? s_u[1] : OVF;
            unsigned ovh = s_u[2] < OVF ? s_u[2] : OVF;
            s_u[1] = ovl; s_u[2] = ovh;
            s_u[7] = aL; s_u[8] = aH;
            s_u[5] = atomicAdd(&g_ncand[slice][0], aL + ovl);
            s_u[6] = atomicAdd(&g_ncand[slice][1], aH + ovh);
        }
        __syncthreads();

        unsigned offL = s_u[5] + wsumL[wrp] + cumL - nl;
        unsigned offH = s_u[6] + wsumH[wrp] + cumH - nh;
        for (unsigned j = 0; j < nl; j++) {
            unsigned gi = offL + j;
            if (gi < CAND_MAX) g_cand[slice][0][gi] = pL[j];
        }
        for (unsigned j = 0; j < nh; j++) {
            unsigned gi = offH + j;
            if (gi < CAND_MAX) g_cand[slice][1][gi] = pH[j];
        }
        for (unsigned j = tid; j < s_u[1]; j += 256) {
            unsigned gi = s_u[5] + s_u[7] + j;
            if (gi < CAND_MAX) g_cand[slice][0][gi] = ovfL[j];
        }
        for (unsigned j = tid; j < s_u[2]; j += 256) {
            unsigned gi = s_u[6] + s_u[8] + j;
            if (gi < CAND_MAX) g_cand[slice][1][gi] = ovfH[j];
        }

        // publish + last-block select
        __threadfence();
        __syncthreads();
        if (tid == 0) s_u[9] = atomicAdd(&g_done[slice], 1u);
        __syncthreads();
        if (s_u[9] == GBLK - 1) {
            __threadfence();   // acquire all gather blocks' writes
            unsigned* hist  = (unsigned*)stL;        // 8 KB of 11.3 KB
            unsigned* tsum  = (unsigned*)stH;
            unsigned* red_u = (unsigned*)stH + 256;
            do_select(slice, 0, hist, tsum, red_u, &s_u[10]);
            __syncthreads();
            do_select(slice, 1, hist, tsum, red_u, &s_u[10]);
            __threadfence();
            __syncthreads();
            if (tid == 0) atomicExch(&g_flag[slice], 1u);
        }
    } else {
        // ---------------- normalize role (reverse slice order) ----------------
        unsigned nt = ticket - gather_total;
        int slice = slices - 1 - (int)(nt / NBLKN);   // newest-gathered first
        int part  = (int)(nt % NBLKN);

        if (tid == 0) {
            unsigned ns = 64;
            while (poll_u32(&g_flag[slice]) == 0u) {
                __nanosleep(ns);
                if (ns < 2048) ns <<= 1;
            }
            __threadfence();
            s_q[0] = __ldcg(&g_q[slice][0]);
            s_q[1] = __ldcg(&g_q[slice][1]);
        }
        __syncthreads();
        float vmin = s_q[0], vmax = s_q[1];
        float a = 1.0f / (vmax - vmin + 1e-8f);
        float b = -vmin * a;

        size_t base = (size_t)slice * N_PER + (size_t)part * NCHUNK;
        const float4* xi = (const float4*)(x + base);
        float4* xo = (float4*)(out + base);

        // 16 float4 per thread; process in 8-deep batches for MLP 8
        #pragma unroll
        for (int half = 0; half < 2; half++) {
            float4 r[8];
            #pragma unroll
            for (int k = 0; k < 8; k++)
                r[k] = xi[tid + (half * 8 + k) * 256];
            #pragma unroll
            for (int k = 0; k < 8; k++) {
                float4 v = r[k];
                v.x = __saturatef(fmaf(v.x, a, b));
                v.y = __saturatef(fmaf(v.y, a, b));
                v.z = __saturatef(fmaf(v.z, a, b));
                v.w = __saturatef(fmaf(v.w, a, b));
                __stcs(&xo[tid + (half * 8 + k) * 256], v);
            }
        }
    }
}

extern "C" void kernel_launch(void* const* d_in, const int* in_sizes, int n_in,
                              void* d_out, int out_size) {
    const float* x = (const float*)d_in[0];
    float* out = (float*)d_out;
    int slices = out_size / N_PER;
    if (slices > MAX_SLICES) slices = MAX_SLICES;
    if (slices < 1) return;

    sample_kernel<<<slices, 256>>>(x);
    mega_kernel<<<slices * TPS, 256>>>(x, out);
}

// round 11
// speedup vs baseline: 1.1680x; 1.1680x over previous
#include <cuda_runtime.h>
#include <stdint.h>

// Problem geometry (x: (32, 7, 512, 512) fp32; per-(B,C) slice quantile over H*W)
#define MAX_SLICES 224
#define N_PER      262144           // 512*512
#define M_SAMP     4096
#define NGROUP     512              // sample groups of 8 contiguous floats
#define CAND_MAX   32768

// Sample-rank brackets among 4096 sorted samples.
#define R_LO 100
#define R_HI 3995

#define NBIN 4096                   // top-12 bits of monotone key

// work partition (R9 skeleton: two-phase tickets, forward order)
#define GBLK   32                   // gather chunks per slice
#define GCHUNK (N_PER / GBLK)       // 8192 elements
#define NBLKN  32                   // normalize chunks per slice
#define NCHUNK (N_PER / NBLKN)      // 8192 elements
#define TPS    (GBLK + NBLKN)
#define STASH  10                   // per-thread stash (mean ~1.6 of 32 elems)
#define SROW   (STASH + 1)          // padded row, conflict-free
#define OVF    512                  // per-block overflow fallback

// ---- static device scratch (no allocations allowed) ----
__device__ float    g_win[MAX_SLICES][2];    // w1 (lo edge), w2 (hi edge)
__device__ float    g_thr[MAX_SLICES];       // symmetric threshold t (or -1)
__device__ unsigned g_ncand[MAX_SLICES][2];
__device__ float    g_cand[MAX_SLICES][2][CAND_MAX];
__device__ float    g_q[MAX_SLICES][2];
__device__ unsigned g_ticket;
__device__ unsigned g_done[MAX_SLICES];
__device__ unsigned g_flag[MAX_SLICES];

// Monotone float <-> uint key
__device__ __forceinline__ unsigned fkey(float f) {
    unsigned u = __float_as_uint(f);
    return (u & 0x80000000u) ? ~u : (u | 0x80000000u);
}
__device__ __forceinline__ float funkey(unsigned k) {
    return (k & 0x80000000u) ? __uint_as_float(k & 0x7FFFFFFFu)
                             : __uint_as_float(~k);
}
__device__ __forceinline__ unsigned poll_u32(const unsigned* p) {
    unsigned v;
    asm volatile("ld.global.cg.u32 %0, [%1];" : "=r"(v) : "l"(p) : "memory");
    return v;
}

// ============================================================
// Kernel 1: per-slice sample histogram -> tail thresholds
// ============================================================
__global__ void sample_kernel(const float* __restrict__ x) {
    __shared__ unsigned hist[NBIN];
    __shared__ unsigned toff[257];
    __shared__ unsigned sh_bin[2];
    __shared__ unsigned wsum[8];

    int slice = blockIdx.x;
    int tid = threadIdx.x;
    const float* xs = x + (size_t)slice * N_PER;

    if (slice == 0 && tid == 0) g_ticket = 0;

    for (int i = tid; i < NBIN; i += 256) hist[i] = 0;
    __syncthreads();

    #pragma unroll
    for (int g = tid; g < NGROUP; g += 256) {
        const float4* gp = (const float4*)(xs + (size_t)g * (N_PER / NGROUP));
        #pragma unroll
        for (int j = 0; j < 2; j++) {
            float4 v = gp[j];
            atomicAdd(&hist[fkey(v.x) >> 20], 1u);
            atomicAdd(&hist[fkey(v.y) >> 20], 1u);
            atomicAdd(&hist[fkey(v.z) >> 20], 1u);
            atomicAdd(&hist[fkey(v.w) >> 20], 1u);
        }
    }
    __syncthreads();

    unsigned s = 0;
    #pragma unroll
    for (int b = 0; b < 16; b++) s += hist[tid * 16 + b];

    int lane = tid & 31, wrp = tid >> 5;
    unsigned cum = s;
    #pragma unroll
    for (int o = 1; o < 32; o <<= 1) {
        unsigned t = __shfl_up_sync(0xffffffffu, cum, o);
        if (lane >= o) cum += t;
    }
    if (lane == 31) wsum[wrp] = cum;
    __syncthreads();
    if (tid == 0) {
        unsigned acc = 0;
        #pragma unroll
        for (int w = 0; w < 8; w++) { unsigned t = wsum[w]; wsum[w] = acc; acc += t; }
    }
    __syncthreads();
    toff[tid] = wsum[wrp] + cum - s;
    if (tid == 255) toff[256] = M_SAMP;
    __syncthreads();

    const int ranks[2] = {R_LO, R_HI};
    if (tid < 2) {
        unsigned R = (unsigned)ranks[tid];
        int lo = 0, hi = 256;
        while (hi - lo > 1) {
            int mid = (lo + hi) >> 1;
            if (toff[mid] <= R) lo = mid; else hi = mid;
        }
        unsigned acc = toff[lo];
        int bin = lo * 16;
        #pragma unroll
        for (int b = 0; b < 16; b++) {
            unsigned h = hist[lo * 16 + b];
            if (acc + h > R) { bin = lo * 16 + b; break; }
            acc += h;
        }
        sh_bin[tid] = (unsigned)bin;
    }
    __syncthreads();

    if (tid == 0) {
        float w1 = funkey((sh_bin[0] + 1u) << 20);   // upper edge of lo-tail bin
        float w2 = funkey(sh_bin[1] << 20);          // lower edge of hi-tail bin
        g_win[slice][0] = w1;
        g_win[slice][1] = w2;
        // symmetric fast path valid iff w1 < 0 < w2
        g_thr[slice] = (w1 < 0.0f && w2 > 0.0f) ? fminf(-w1, w2) : -1.0f;
        g_ncand[slice][0] = 0; g_ncand[slice][1] = 0;
        g_done[slice] = 0;
        g_flag[slice] = 0;
    }
}

// ============================================================
// Inline select: exact radix-select among candidates of (slice, w).
// w=0: stash contains ALL f below its threshold  -> base count 0.
// w=1: stash contains ALL f >= its threshold     -> base = N - n.
// ============================================================
__device__ void do_select(int slice, int w, unsigned* hist, unsigned* tsum,
                          unsigned* red_u, volatile unsigned* sh2) {
    int tid = threadIdx.x;
    unsigned n_raw = g_ncand[slice][w];
    unsigned n = n_raw > CAND_MAX ? CAND_MAX : n_raw;
    unsigned cnt = (w == 0) ? 0u : (unsigned)N_PER - n_raw;

    double pos  = (w == 0) ? 0.01 * (double)(N_PER - 1) : 0.99 * (double)(N_PER - 1);
    long long K = (long long)pos;
    double frac = pos - (double)K;

    if (n < 2) {
        if (tid == 0) g_q[slice][w] = (n == 1) ? g_cand[slice][w][0] : 0.0f;
        return;
    }
    long long rl = K - (long long)cnt;
    if (rl < 0) rl = 0;
    if (rl > (long long)n - 2) rl = (long long)n - 2;
    int r = (int)rl;
    const float* cand = g_cand[slice][w];

    unsigned prefix = 0, pmask = 0;
    int rrem = r;
    const int shifts[3] = {21, 10, 0};
    const int bitsv[3]  = {11, 11, 10};
    #pragma unroll
    for (int p = 0; p < 3; p++) {
        int shift = shifts[p];
        unsigned nb = 1u << bitsv[p];
        unsigned dmask = nb - 1u;
        unsigned per = nb / 256;
        for (unsigned i = tid; i < 2048; i += 256) hist[i] = 0;
        __syncthreads();
        for (unsigned i = tid; i < n; i += 256) {
            unsigned u = fkey(cand[i]);
            if ((u & pmask) == prefix)
                atomicAdd(&hist[(u >> shift) & dmask], 1u);
        }
        __syncthreads();
        unsigned s = 0;
        for (unsigned q2 = 0; q2 < per; q2++) s += hist[tid * per + q2];
        tsum[tid] = s;
        __syncthreads();

        if (tid < 32) {
            unsigned part[8];
            unsigned ls = 0;
            #pragma unroll
            for (int j = 0; j < 8; j++) { part[j] = tsum[tid * 8 + j]; ls += part[j]; }
            unsigned cum = ls;
            #pragma unroll
            for (int o = 1; o < 32; o <<= 1) {
                unsigned t = __shfl_up_sync(0xffffffffu, cum, o);
                if (tid >= o) cum += t;
            }
            unsigned excl = cum - ls;
            unsigned ball = __ballot_sync(0xffffffffu, cum > (unsigned)rrem);
            int cross = __ffs(ball) - 1;
            if (tid == cross) {
                unsigned acc = excl;
                int tc = tid * 8;
                #pragma unroll
                for (int j = 0; j < 8; j++) {
                    if (acc + part[j] > (unsigned)rrem) { tc = tid * 8 + j; break; }
                    acc += part[j];
                }
                unsigned d = (unsigned)tc * per;
                for (unsigned b = 0; b < per; b++) {
                    unsigned h = hist[tc * per + b];
                    if (acc + h > (unsigned)rrem) { d = (unsigned)tc * per + b; break; }
                    acc += h;
                }
                sh2[0] = d;
                sh2[1] = (unsigned)rrem - acc;
            }
        }
        __syncthreads();
        prefix |= sh2[0] << shift;
        pmask  |= dmask << shift;
        rrem = (int)sh2[1];
        __syncthreads();
    }
    unsigned v0key = prefix;

    unsigned cle = 0, mgt = 0xFFFFFFFFu;
    for (unsigned i = tid; i < n; i += 256) {
        unsigned u = fkey(cand[i]);
        cle += (u <= v0key);
        if (u > v0key && u < mgt) mgt = u;
    }
    red_u[tid] = cle; __syncthreads();
    for (int o = 128; o; o >>= 1) {
        if (tid < o) red_u[tid] += red_u[tid + o];
        __syncthreads();
    }
    unsigned cle_tot = red_u[0]; __syncthreads();
    red_u[tid] = mgt; __syncthreads();
    for (int o = 128; o; o >>= 1) {
        if (tid < o) red_u[tid] = (red_u[tid + o] < red_u[tid]) ? red_u[tid + o] : red_u[tid];
        __syncthreads();
    }
    unsigned mgt_tot = red_u[0];
    __syncthreads();

    if (tid == 0) {
        unsigned v1key = (cle_tot >= (unsigned)(r + 2)) ? v0key
                       : ((mgt_tot != 0xFFFFFFFFu) ? mgt_tot : v0key);
        double v0 = (double)funkey(v0key);
        double v1 = (double)funkey(v1key);
        g_q[slice][w] = (float)(v0 + frac * (v1 - v0));
    }
}

// ============================================================
// Mega kernel (R9 skeleton, forward order): gather tickets first,
// then normalize tickets. Gather hot path: one |f|>=t predicate
// OR-folded per float4 -> single rare branch.
// ============================================================
__global__ void __launch_bounds__(256) mega_kernel(const float* __restrict__ x,
                                                   float* __restrict__ out) {
    __shared__ float stL[256 * SROW];        // 11.3 KB
    __shared__ float stH[256 * SROW];        // 11.3 KB (aliased in select)
    __shared__ float ovfL[OVF], ovfH[OVF];   // 4 KB
    __shared__ unsigned s_u[16];
    __shared__ unsigned wsumL[8], wsumH[8];
    __shared__ float s_q[2];

    int tid = threadIdx.x;
    int lane = tid & 31, wrp = tid >> 5;
    int slices = gridDim.x / TPS;
    unsigned gather_total = (unsigned)(GBLK * slices);

    if (tid == 0) {
        s_u[0] = atomicAdd(&g_ticket, 1u);
        s_u[1] = 0; s_u[2] = 0;
    }
    __syncthreads();
    unsigned ticket = s_u[0];

    if (ticket < gather_total) {
        // ---------------- gather role ----------------
        int slice = (int)(ticket / GBLK);
        int part  = (int)(ticket % GBLK);
        const float4* xs = (const float4*)(x + (size_t)slice * N_PER
                                             + (size_t)part * GCHUNK);
        float thr = g_thr[slice];

        float* pL = &stL[tid * SROW];
        float* pH = &stH[tid * SROW];
        unsigned nl = 0, nh = 0;

        if (thr >= 0.0f) {
            // symmetric fast path: 4x FSETP(|f|,t) OR-folded, one branch/float4
            #pragma unroll
            for (int kb = 0; kb < 2; kb++) {
                float4 r[4];
                #pragma unroll
                for (int k = 0; k < 4; k++)
                    r[k] = xs[tid + (kb * 4 + k) * 256];
                #pragma unroll
                for (int k = 0; k < 4; k++) {
                    float4 v = r[k];
                    bool any = (fabsf(v.x) >= thr) | (fabsf(v.y) >= thr)
                             | (fabsf(v.z) >= thr) | (fabsf(v.w) >= thr);
                    if (any) {                       // ~18% of float4s
                        float vv[4] = {v.x, v.y, v.z, v.w};
                        #pragma unroll
                        for (int c = 0; c < 4; c++) {
                            float f = vv[c];
                            if (fabsf(f) >= thr) {
                                if (f < 0.0f) {
                                    if (nl < STASH) pL[nl++] = f;
                                    else { unsigned o = atomicAdd(&s_u[1], 1u); if (o < OVF) ovfL[o] = f; }
                                } else {
                                    if (nh < STASH) pH[nh++] = f;
                                    else { unsigned o = atomicAdd(&s_u[2], 1u); if (o < OVF) ovfH[o] = f; }
                                }
                            }
                        }
                    }
                }
            }
        } else {
            // general fallback: two-compare path
            float w1 = g_win[slice][0];
            float w2 = g_win[slice][1];
            #pragma unroll 4
            for (int k = 0; k < GCHUNK / 4 / 256; k++) {
                float4 v = xs[tid + k * 256];
                float vv[4] = {v.x, v.y, v.z, v.w};
                #pragma unroll
                for (int c = 0; c < 4; c++) {
                    float f = vv[c];
                    if (f < w1) {
                        if (nl < STASH) pL[nl++] = f;
                        else { unsigned o = atomicAdd(&s_u[1], 1u); if (o < OVF) ovfL[o] = f; }
                    }
                    if (f >= w2) {
                        if (nh < STASH) pH[nh++] = f;
                        else { unsigned o = atomicAdd(&s_u[2], 1u); if (o < OVF) ovfH[o] = f; }
                    }
                }
            }
        }

        // block exclusive scan of stash counts
        unsigned cumL = nl, cumH = nh;
        #pragma unroll
        for (int o = 1; o < 32; o <<= 1) {
            unsigned tL = __shfl_up_sync(0xffffffffu, cumL, o);
            unsigned tH = __shfl_up_sync(0xffffffffu, cumH, o);
            if (lane >= o) { cumL += tL; cumH += tH; }
        }
        if (lane == 31) { wsumL[wrp] = cumL; wsumH[wrp] = cumH; }
        __syncthreads();

        if (tid == 0) {
            unsigned aL = 0, aH = 0;
            #pragma unroll
            for (int w = 0; w < 8; w++) {
                unsigned tL = wsumL[w], tH = wsumH[w];
                wsumL[w] = aL; wsumH[w] = aH;
                aL += tL; aH += tH;
            }
            unsigned ovl = s_u[1] < OVF ? s_u[1] : OVF;
            unsigned ovh = s_u[2] < OVF ? s_u[2] : OVF;
            s_u[1] = ovl; s_u[2] = ovh;
            s_u[7] = aL; s_u[8] = aH;
            s_u[5] = atomicAdd(&g_ncand[slice][0], aL + ovl);
            s_u[6] = atomicAdd(&g_ncand[slice][1], aH + ovh);
        }
        __syncthreads();

        unsigned offL = s_u[5] + wsumL[wrp] + cumL - nl;
        unsigned offH = s_u[6] + wsumH[wrp] + cumH - nh;
        for (unsigned j = 0; j < nl; j++) {
            unsigned gi = offL + j;
            if (gi < CAND_MAX) g_cand[slice][0][gi] = pL[j];
        }
        for (unsigned j = 0; j < nh; j++) {
            unsigned gi = offH + j;
            if (gi < CAND_MAX) g_cand[slice][1][gi] = pH[j];
        }
        for (unsigned j = tid; j < s_u[1]; j += 256) {
            unsigned gi = s_u[5] + s_u[7] + j;
            if (gi < CAND_MAX) g_cand[slice][0][gi] = ovfL[j];
        }
        for (unsigned j = tid; j < s_u[2]; j += 256) {
            unsigned gi = s_u[6] + s_u[8] + j;
            if (gi < CAND_MAX) g_cand[slice][1][gi] = ovfH[j];
        }

        // publish + last-block select
        __threadfence();
        __syncthreads();
        if (tid == 0) s_u[9] = atomicAdd(&g_done[slice], 1u);
        __syncthreads();
        if (s_u[9] == GBLK - 1) {
            __threadfence();   // acquire all gather blocks' writes
            unsigned* hist  = (unsigned*)stL;
            unsigned* tsum  = (unsigned*)stH;
            unsigned* red_u = (unsigned*)stH + 256;
            do_select(slice, 0, hist, tsum, red_u, &s_u[10]);
            __syncthreads();
            do_select(slice, 1, hist, tsum, red_u, &s_u[10]);
            __threadfence();
            __syncthreads();
            if (tid == 0) atomicExch(&g_flag[slice], 1u);
        }
    } else {
        // ---------------- normalize role (forward order) ----------------
        unsigned nt = ticket - gather_total;
        int slice = (int)(nt / NBLKN);
        int part  = (int)(nt % NBLKN);

        if (tid == 0) {
            unsigned ns = 64;
            while (poll_u32(&g_flag[slice]) == 0u) {
                __nanosleep(ns);
                if (ns < 2048) ns <<= 1;
            }
            __threadfence();
            s_q[0] = __ldcg(&g_q[slice][0]);
            s_q[1] = __ldcg(&g_q[slice][1]);
        }
        __syncthreads();
        float vmin = s_q[0], vmax = s_q[1];
        float a = 1.0f / (vmax - vmin + 1e-8f);
        float b = -vmin * a;

        size_t base = (size_t)slice * N_PER + (size_t)part * NCHUNK;
        const float4* xi = (const float4*)(x + base);
        float4* xo = (float4*)(out + base);
        const int NV = NCHUNK / 4;       // 2048
        #pragma unroll 4
        for (int i = tid; i < NV; i += 256) {
            float4 v = __ldcg(&xi[i]);
            v.x = __saturatef(fmaf(v.x, a, b));
            v.y = __saturatef(fmaf(v.y, a, b));
            v.z = __saturatef(fmaf(v.z, a, b));
            v.w = __saturatef(fmaf(v.w, a, b));
            __stcs(&xo[i], v);               // streaming store
        }
    }
}

extern "C" void kernel_launch(void* const* d_in, const int* in_sizes, int n_in,
                              void* d_out, int out_size) {
    const float* x = (const float*)d_in[0];
    float* out = (float*)d_out;
    int slices = out_size / N_PER;
    if (slices > MAX_SLICES) slices = MAX_SLICES;
    if (slices < 1) return;

    sample_kernel<<<slices, 256>>>(x);
    mega_kernel<<<slices * TPS, 256>>>(x, out);
}